// round 10
// baseline (speedup 1.0000x reference)
#include <cuda_runtime.h>
#include <math.h>

#define NB 16
#define NT 128
#define NI 8
#define ND 128
#define NRB (NT*NB)   // 2048

// scratch (allowed: __device__ globals; zero-initialized)
__device__ float g_Xd [NRB*ND];
__device__ float g_T  [NRB*ND];
__device__ float g_Z  [NRB*ND];
__device__ float g_Wqk[ND*ND];   // Wq @ Wk^T   ([d][n])
__device__ float g_Wvo[ND*ND];   // Wv @ Wo

// dynamic smem layout for k_attn (floats)
#define OFF_WE   0
#define OFF_BE   (OFF_WE  + 1024)
#define OFF_G1   (OFF_BE  + 128)
#define OFF_B1   (OFF_G1  + 128)
#define OFF_TS   (OFF_B1  + 128)
#define OFF_LG   (OFF_TS  + 128)
#define OFF_SW   (OFF_LG  + 128)
#define OFF_RED  (OFF_SW  + 128)
#define OFF_ML   (OFF_RED + 128)
#define OFF_XS   (OFF_ML  + 4)
#define ATTN_FLOATS (OFF_XS + 128*132)
#define ATTN_SMEM   (ATTN_FLOATS*4)   // 75280 bytes

// mask is a bool array delivered as 32-bit elements (int32 0/1 or float32 0.0/1.0).
__device__ __forceinline__ float mask_f(const unsigned int* __restrict__ m, int idx){
    return (m[idx] != 0u) ? 1.0f : 0.0f;
}

__device__ __forceinline__ float gelu_f(float x){
    // jax gelu (tanh approx) == x * sigmoid(2*g), g = sqrt(2/pi)*(x + 0.044715 x^3)
    float x2 = x*x;
    float g  = x*(0.7978845608028654f + 0.03567740813634427f*x2);
    float e  = __expf(-2.0f*g);
    return x / (1.0f + e);
}

// ---------------------------------------------------------------------------
// k_pre: fused independent prep work, one launch, 256 threads/CTA
//   blocks [0,1024):    Xd diag rows (2 rows per CTA)
//   blocks [1024,1040): Wqk = Wq @ Wk^T  (8 out-rows per CTA, tiled)
//   blocks [1040,1056): Wvo = Wv @ Wo    (8 out-rows per CTA, tiled)
//   blocks [1056,1073): bool outputs as float
// ---------------------------------------------------------------------------
__global__ void __launch_bounds__(256) k_pre(
    const float* __restrict__ vec, const unsigned int* __restrict__ mask,
    const float* __restrict__ We,  const float* __restrict__ be,
    const float* __restrict__ g1,  const float* __restrict__ b1,
    const float* __restrict__ Wq,  const float* __restrict__ Wk,
    const float* __restrict__ Wv,  const float* __restrict__ Wo,
    float* __restrict__ out, int do_masks)
{
    __shared__ float smbuf[5248];
    int bi  = blockIdx.x;
    int tid = threadIdx.x;

    if (bi < 1024){
        // ---- diag rows: rb = bi*2 + h
        float* v8s = smbuf;        // 2*8
        float* red = smbuf + 16;   // 2*8
        int h = tid >> 7, d = tid & 127;
        int rb = bi*2 + h; int r = rb >> 4, b = rb & 15;
        const float* vp = vec + ((b*NT + r)*NT + r)*NI;
        if (d < 8) v8s[h*8 + d] = vp[d];
        float mf = mask_f(mask, (b*NT + r)*NT + r);
        __syncthreads();
        float y = be[d];
        #pragma unroll
        for (int i = 0; i < 8; i++) y += v8s[h*8 + i]*We[i*ND + d];
        y = gelu_f(y) * mf;
        float s1 = y, s2 = y*y;
        #pragma unroll
        for (int o = 16; o; o >>= 1){
            s1 += __shfl_xor_sync(0xffffffffu, s1, o);
            s2 += __shfl_xor_sync(0xffffffffu, s2, o);
        }
        int w = (tid >> 5) & 3, lane = tid & 31;
        if (lane == 0){ red[h*8 + w] = s1; red[h*8 + 4 + w] = s2; }
        __syncthreads();
        s1 = red[h*8+0]+red[h*8+1]+red[h*8+2]+red[h*8+3];
        s2 = red[h*8+4]+red[h*8+5]+red[h*8+6]+red[h*8+7];
        float mu  = s1 * (1.0f/128.0f);
        float var = s2 * (1.0f/128.0f) - mu*mu;
        g_Xd[rb*ND + d] = (y - mu)*rsqrtf(var + 1e-5f)*g1[d] + b1[d];
    } else if (bi < 1040){
        // ---- Wqk[m][n] = sum_e Wq[m][e]*Wk[n][e], rows m0..m0+7
        float* sA = smbuf;          // 8*128
        float* sB = smbuf + 1024;   // 32*129 (pitch 129, conflict-free scalar)
        int m0 = (bi - 1024)*8;
        *(float4*)&sA[tid*4] = *(const float4*)(Wq + m0*ND + tid*4);
        int m = tid >> 5, nl = tid & 31;
        for (int nt = 0; nt < 4; nt++){
            int n0 = nt*32;
            #pragma unroll
            for (int i = 0; i < 4; i++){
                int fi = tid + i*256;        // float4 index 0..1023
                int rowk = fi >> 5, col4 = fi & 31;
                float4 v = *(const float4*)(Wk + (n0+rowk)*ND + col4*4);
                float* dst = &sB[rowk*129 + col4*4];
                dst[0]=v.x; dst[1]=v.y; dst[2]=v.z; dst[3]=v.w;
            }
            __syncthreads();
            float a = 0.0f;
            #pragma unroll 8
            for (int e = 0; e < 128; e++)
                a += sA[m*128 + e] * sB[nl*129 + e];
            g_Wqk[(m0+m)*ND + n0 + nl] = a;
            __syncthreads();
        }
    } else if (bi < 1056){
        // ---- Wvo[m][n] = sum_e Wv[m][e]*Wo[e][n], rows m0..m0+7
        float* sA = smbuf;          // 8*128
        float* sB = smbuf + 1024;   // 32*132 (pitch 132)
        int m0 = (bi - 1040)*8;
        *(float4*)&sA[tid*4] = *(const float4*)(Wv + m0*ND + tid*4);
        int m = tid >> 5, tx = tid & 31;
        float4 acc = make_float4(0.f,0.f,0.f,0.f);
        for (int e0 = 0; e0 < 128; e0 += 32){
            #pragma unroll
            for (int i = 0; i < 4; i++){
                int fi = tid + i*256;
                int ee = fi >> 5, col4 = fi & 31;
                *(float4*)&sB[ee*132 + col4*4] = *(const float4*)(Wo + (e0+ee)*ND + col4*4);
            }
            __syncthreads();
            #pragma unroll 8
            for (int ee = 0; ee < 32; ee++){
                float a = sA[m*128 + e0 + ee];
                float4 b4 = *(float4*)&sB[ee*132 + tx*4];
                acc.x += a*b4.x; acc.y += a*b4.y; acc.z += a*b4.z; acc.w += a*b4.w;
            }
            __syncthreads();
        }
        *(float4*)&g_Wvo[(m0+m)*ND + tx*4] = acc;
    } else if (do_masks){
        int idx = (bi - 1056)*256 + tid;
        if (idx < 2048){
            int b = idx >> 7, t = idx & 127;
            out[262144 + idx] = (mask[(b*NT + t)*NT + t] != 0u) ? 0.0f : 1.0f;   // ~seq^T
        } else if (idx < 4096){
            int k = idx - 2048; int t = k >> 4, b = k & 15;
            out[264192 + k] = (mask[(b*NT + t)*NT + t] != 0u) ? 1.0f : 0.0f;     // seq
        } else if (idx < 4224){
            out[266240 + (idx - 4096)] = 1.0f;                                    // ones
        }
    }
}

// ---------------------------------------------------------------------------
// T = Xd @ Wqk  — tiled GEMM, 16-row CTAs (grid 128), both operands in smem
// Threads owning two inactive rows skip the FMA loop (loads/barriers intact).
// ---------------------------------------------------------------------------
__global__ void __launch_bounds__(256) k_qt(const unsigned int* __restrict__ mask)
{
    __shared__ float sA[16*33];
    __shared__ float sB[32*132];
    int tid = threadIdx.x;
    int rb0 = blockIdx.x*16;
    int tx = tid & 31, ty = tid >> 5;
    int r0 = ty*2, r1 = r0 + 1, c4 = tx*4;
    // activity of my two rows (diag mask)
    int rb_a = rb0 + r0, rb_b = rb0 + r1;
    int ra = rb_a >> 4, ba = rb_a & 15;
    int rbq = rb_b >> 4, bb = rb_b & 15;
    bool act = (mask[(ba*NT + ra)*NT + ra] != 0u) || (mask[(bb*NT + rbq)*NT + rbq] != 0u);

    float acc[8];
    #pragma unroll
    for (int j = 0; j < 8; j++) acc[j] = 0.0f;

    for (int k0 = 0; k0 < 128; k0 += 32){
        #pragma unroll
        for (int i = 0; i < 2; i++){
            int idx = tid + i*256; int row = idx >> 5, kk = idx & 31;
            sA[row*33 + kk] = g_Xd[(rb0+row)*ND + k0 + kk];
        }
        #pragma unroll
        for (int i = 0; i < 4; i++){
            int fi = tid + i*256; int kk = fi >> 5, cf = fi & 31;
            *(float4*)&sB[kk*132 + cf*4] = *(const float4*)(g_Wqk + (k0+kk)*ND + cf*4);
        }
        __syncthreads();
        if (act){
            #pragma unroll
            for (int kk = 0; kk < 32; kk++){
                float a0 = sA[r0*33 + kk], a1 = sA[r1*33 + kk];
                float4 b = *(float4*)&sB[kk*132 + c4];
                acc[0] += a0*b.x; acc[1] += a0*b.y; acc[2] += a0*b.z; acc[3] += a0*b.w;
                acc[4] += a1*b.x; acc[5] += a1*b.y; acc[6] += a1*b.z; acc[7] += a1*b.w;
            }
        }
        __syncthreads();
    }
    *(float4*)&g_T[(rb0+r0)*ND + c4] = make_float4(acc[0],acc[1],acc[2],acc[3]);
    *(float4*)&g_T[(rb0+r1)*ND + c4] = make_float4(acc[4],acc[5],acc[6],acc[7]);
}

// ---------------------------------------------------------------------------
// Fused attention. One CTA per (r,b), 256 threads, dyn smem.
// Early-exit if diagonal masked; masked c-rows skipped.
// ---------------------------------------------------------------------------
__global__ void __launch_bounds__(256) k_attn(
    const float* __restrict__ vec, const unsigned int* __restrict__ mask,
    const float* __restrict__ We,  const float* __restrict__ be,
    const float* __restrict__ g1,  const float* __restrict__ b1)
{
    extern __shared__ float sm[];
    float* sWe  = sm + OFF_WE;
    float* sbe  = sm + OFF_BE;
    float* sg1  = sm + OFF_G1;
    float* sb1  = sm + OFF_B1;
    float* ts   = sm + OFF_TS;
    float* slg  = sm + OFF_LG;
    float* sw   = sm + OFF_SW;
    float* sred = sm + OFF_RED;
    float* sml  = sm + OFF_ML;
    float* sxs  = sm + OFF_XS;

    int tid = threadIdx.x;
    int rb = blockIdx.x; int r = rb >> 4; int b = rb & 15;

    // early exit: masked diagonal -> output row zeroed in k_out anyway
    if (mask[(b*NT + r)*NT + r] == 0u) return;

    #pragma unroll
    for (int i = 0; i < 4; i++) sWe[tid + i*256] = We[tid + i*256];
    if (tid < 128){
        sbe[tid] = be[tid]; sg1[tid] = g1[tid]; sb1[tid] = b1[tid];
        ts[tid]  = g_T[rb*ND + tid] * 0.08838834764831845f;   // 1/sqrt(128)
    }
    __syncthreads();

    // phase 1a: embed+gelu+LN1 for c-row = tid>>1, d-half = tid&1
    int row = tid >> 1, half = tid & 1, d0 = 64*half;
    int lane = tid & 31;
    unsigned pmask = 3u << (lane & ~1);   // 2-lane pair mask (divergence-safe)
    float mf = mask_f(mask, (b*NT + r)*NT + row);
    bool active_row = (mf != 0.0f);   // row==r always active (diag unmasked)

    if (active_row){
        const float* vp = vec + (((b*NT + r)*NT) + row)*NI;
        float4 vA = *(const float4*)vp;
        float4 vB = *(const float4*)(vp + 4);
        float v8r[8] = {vA.x,vA.y,vA.z,vA.w,vB.x,vB.y,vB.z,vB.w};

        float y[64];
        float s1 = 0.0f, s2 = 0.0f;
        #pragma unroll
        for (int j = 0; j < 16; j++){
            int d = d0 + 4*j;
            float4 a4 = *(const float4*)(sbe + d);
            #pragma unroll
            for (int i = 0; i < 8; i++){
                float4 w4 = *(const float4*)(sWe + i*128 + d);
                a4.x += v8r[i]*w4.x; a4.y += v8r[i]*w4.y;
                a4.z += v8r[i]*w4.z; a4.w += v8r[i]*w4.w;
            }
            a4.x = gelu_f(a4.x); a4.y = gelu_f(a4.y);
            a4.z = gelu_f(a4.z); a4.w = gelu_f(a4.w);
            y[4*j+0]=a4.x; y[4*j+1]=a4.y; y[4*j+2]=a4.z; y[4*j+3]=a4.w;
            s1 += a4.x + a4.y + a4.z + a4.w;
            s2 += a4.x*a4.x + a4.y*a4.y + a4.z*a4.z + a4.w*a4.w;
        }
        s1 += __shfl_xor_sync(pmask, s1, 1);
        s2 += __shfl_xor_sync(pmask, s2, 1);
        float mu   = s1*(1.0f/128.0f);
        float var  = s2*(1.0f/128.0f) - mu*mu;
        float rstd = rsqrtf(var + 1e-5f);
        #pragma unroll
        for (int j = 0; j < 16; j++){
            int d = d0 + 4*j;
            float4 g4 = *(const float4*)(sg1 + d);
            float4 b4 = *(const float4*)(sb1 + d);
            float4 x4;
            x4.x = (y[4*j+0]-mu)*rstd*g4.x + b4.x;
            x4.y = (y[4*j+1]-mu)*rstd*g4.y + b4.y;
            x4.z = (y[4*j+2]-mu)*rstd*g4.z + b4.z;
            x4.w = (y[4*j+3]-mu)*rstd*g4.w + b4.w;
            *(float4*)(sxs + row*132 + d) = x4;
        }
    } else {
        // masked row: weight will be exactly 0; store zeros to keep phase 3 clean
        float4 z4 = make_float4(0.f,0.f,0.f,0.f);
        #pragma unroll
        for (int j = 0; j < 16; j++) *(float4*)(sxs + row*132 + d0 + 4*j) = z4;
        if (half == 0) slg[row] = -1e9f;
    }
    __syncthreads();

    // phase 1c: logits for active rows (pair-mask shuffle; divergent-safe)
    if (active_row){
        float dotp = 0.0f;
        #pragma unroll
        for (int j = 0; j < 16; j++){
            int d = d0 + 4*j;
            float4 x4 = *(const float4*)(sxs + row*132 + d);
            float4 t4 = *(const float4*)(ts + d);
            dotp += x4.x*t4.x + x4.y*t4.y + x4.z*t4.z + x4.w*t4.w;
        }
        dotp += __shfl_xor_sync(pmask, dotp, 1);
        if (half == 0) slg[row] = dotp;
    }
    __syncthreads();

    // phase 2: flat softmax over 128 logits (warp 0; convergent)
    if (tid < 32){
        float lgv[4];
        #pragma unroll
        for (int k = 0; k < 4; k++) lgv[k] = slg[tid + 32*k];
        float m = fmaxf(fmaxf(lgv[0],lgv[1]), fmaxf(lgv[2],lgv[3]));
        #pragma unroll
        for (int o = 16; o; o >>= 1) m = fmaxf(m, __shfl_xor_sync(0xffffffffu, m, o));
        float e[4], s = 0.0f;
        #pragma unroll
        for (int k = 0; k < 4; k++){ e[k] = __expf(lgv[k]-m); s += e[k]; }
        #pragma unroll
        for (int o = 16; o; o >>= 1) s += __shfl_xor_sync(0xffffffffu, s, o);
        #pragma unroll
        for (int k = 0; k < 4; k++) sw[tid + 32*k] = e[k];
        if (tid == 0) sml[0] = s;
    }
    __syncthreads();

    // phase 3: z[dz] = sum_c w[c] * x[c][dz]
    int dz = tid & 127, h = tid >> 7;
    float z = 0.0f;
    const float* xp = sxs + (h*64)*132 + dz;
    const float* wp = sw + h*64;
    #pragma unroll 8
    for (int c = 0; c < 64; c++) z += wp[c]*xp[c*132];
    if (h == 1) sred[dz] = z;
    __syncthreads();
    if (h == 0) g_Z[rb*ND + dz] = (z + sred[dz]) / sml[0];
}

// ---------------------------------------------------------------------------
// [E|G] = Z @ [Wv|Wvo]; t = gelu(G+bo)+E; out = LN2(t)*seq
// 16-row CTAs (grid 128), tiled GEMM N=256, B in smem, C reuses B smem.
// Warps owning two inactive rows skip the FMA loop.
// ---------------------------------------------------------------------------
__global__ void __launch_bounds__(256) k_out(
    const float* __restrict__ Wv, const float* __restrict__ bo,
    const float* __restrict__ g2, const float* __restrict__ b2,
    const unsigned int* __restrict__ mask, float* __restrict__ out)
{
    __shared__ float sA[16*33];
    __shared__ float sB[32*260];    // also reused as sC[16*260] post-loop
    int tid = threadIdx.x;
    int rb0 = blockIdx.x*16;
    int tx = tid & 31, ty = tid >> 5;
    int r0 = ty*2, r1 = r0 + 1, c8 = tx*8;
    // activity of my two rows
    int rb_a = rb0 + r0, rb_b = rb0 + r1;
    int ra = rb_a >> 4, ba = rb_a & 15;
    int rq = rb_b >> 4, bq = rb_b & 15;
    bool act = (mask[(ba*NT + ra)*NT + ra] != 0u) || (mask[(bq*NT + rq)*NT + rq] != 0u);

    float acc[16];
    #pragma unroll
    for (int j = 0; j < 16; j++) acc[j] = 0.0f;

    for (int k0 = 0; k0 < 128; k0 += 32){
        #pragma unroll
        for (int i = 0; i < 2; i++){
            int idx = tid + i*256; int row = idx >> 5, kk = idx & 31;
            sA[row*33 + kk] = g_Z[(rb0+row)*ND + k0 + kk];
        }
        #pragma unroll
        for (int i = 0; i < 8; i++){
            int fi = tid + i*256; int kk = fi >> 6, cf = fi & 63;
            const float* src = (cf < 32) ? (Wv + (k0+kk)*ND + cf*4)
                                         : (g_Wvo + (k0+kk)*ND + (cf-32)*4);
            *(float4*)&sB[kk*260 + cf*4] = *(const float4*)src;
        }
        __syncthreads();
        if (act){
            #pragma unroll
            for (int kk = 0; kk < 32; kk++){
                float a0 = sA[r0*33 + kk], a1 = sA[r1*33 + kk];
                float4 bx = *(float4*)&sB[kk*260 + c8];
                float4 by = *(float4*)&sB[kk*260 + c8 + 4];
                acc[0] += a0*bx.x; acc[1] += a0*bx.y; acc[2] += a0*bx.z; acc[3] += a0*bx.w;
                acc[4] += a0*by.x; acc[5] += a0*by.y; acc[6] += a0*by.z; acc[7] += a0*by.w;
                acc[8] += a1*bx.x; acc[9] += a1*bx.y; acc[10]+= a1*bx.z; acc[11]+= a1*bx.w;
                acc[12]+= a1*by.x; acc[13]+= a1*by.y; acc[14]+= a1*by.z; acc[15]+= a1*by.w;
            }
        }
        __syncthreads();
    }
    // stage C into reused sB (E in cols [0,128), G in [128,256))
    *(float4*)&sB[r0*260 + c8    ] = make_float4(acc[0],acc[1],acc[2],acc[3]);
    *(float4*)&sB[r0*260 + c8 + 4] = make_float4(acc[4],acc[5],acc[6],acc[7]);
    *(float4*)&sB[r1*260 + c8    ] = make_float4(acc[8],acc[9],acc[10],acc[11]);
    *(float4*)&sB[r1*260 + c8 + 4] = make_float4(acc[12],acc[13],acc[14],acc[15]);
    __syncthreads();

    // epilogue: warp ty handles rows r0,r1; lane owns d-quad tx*4
    int d4 = tx*4;
    float4 bo4 = *(const float4*)(bo + d4);
    float4 g24 = *(const float4*)(g2 + d4);
    float4 b24 = *(const float4*)(b2 + d4);
    #pragma unroll
    for (int rr = 0; rr < 2; rr++){
        int row = ty*2 + rr;
        float4 E = *(float4*)&sB[row*260 + d4];
        float4 G = *(float4*)&sB[row*260 + 128 + d4];
        float4 t;
        t.x = gelu_f(G.x + bo4.x) + E.x;
        t.y = gelu_f(G.y + bo4.y) + E.y;
        t.z = gelu_f(G.z + bo4.z) + E.z;
        t.w = gelu_f(G.w + bo4.w) + E.w;
        float s1 = t.x + t.y + t.z + t.w;
        float s2 = t.x*t.x + t.y*t.y + t.z*t.z + t.w*t.w;
        #pragma unroll
        for (int o = 16; o; o >>= 1){
            s1 += __shfl_xor_sync(0xffffffffu, s1, o);
            s2 += __shfl_xor_sync(0xffffffffu, s2, o);
        }
        float mu   = s1*(1.0f/128.0f);
        float var  = s2*(1.0f/128.0f) - mu*mu;
        float rstd = rsqrtf(var + 1e-5f);
        int rbg = rb0 + row; int r = rbg >> 4, bb = rbg & 15;
        float sf = mask_f(mask, (bb*NT + r)*NT + r);
        float4 o4;
        o4.x = ((t.x - mu)*rstd*g24.x + b24.x)*sf;
        o4.y = ((t.y - mu)*rstd*g24.y + b24.y)*sf;
        o4.z = ((t.z - mu)*rstd*g24.z + b24.z)*sf;
        o4.w = ((t.w - mu)*rstd*g24.w + b24.w)*sf;
        *(float4*)(out + rbg*ND + d4) = o4;
    }
}

extern "C" void kernel_launch(void* const* d_in, const int* in_sizes, int n_in,
                              void* d_out, int out_size)
{
    const float*        vec  = (const float*)d_in[0];
    const unsigned int* mask = (const unsigned int*)d_in[1];
    const float* We = (const float*)d_in[2];
    const float* be = (const float*)d_in[3];
    const float* g1 = (const float*)d_in[4];
    const float* b1 = (const float*)d_in[5];
    const float* Wq = (const float*)d_in[6];
    const float* Wk = (const float*)d_in[7];
    const float* Wv = (const float*)d_in[8];
    const float* Wo = (const float*)d_in[9];
    const float* bo = (const float*)d_in[10];
    const float* g2 = (const float*)d_in[11];
    const float* b2 = (const float*)d_in[12];
    float* out = (float*)d_out;

    cudaFuncSetAttribute(k_attn, cudaFuncAttributeMaxDynamicSharedMemorySize, ATTN_SMEM);

    int do_masks = (out_size >= 266368) ? 1 : 0;
    k_pre <<<1073, 256>>>(vec, mask, We, be, g1, b1, Wq, Wk, Wv, Wo, out, do_masks);
    k_qt  <<<NRB/16, 256>>>(mask);
    k_attn<<<NRB, 256, ATTN_SMEM>>>(vec, mask, We, be, g1, b1);
    k_out <<<NRB/16, 256>>>(Wv, bo, g2, b2, mask, out);
    (void)in_sizes; (void)n_in;
}

// round 11
// speedup vs baseline: 1.4530x; 1.4530x over previous
#include <cuda_runtime.h>
#include <math.h>

#define NB 16
#define NT 128
#define NI 8
#define ND 128
#define NRB (NT*NB)   // 2048

// scratch (allowed: __device__ globals; zero-initialized)
__device__ float g_Xd [NRB*ND];
__device__ float g_T  [NRB*ND];
__device__ float g_Z  [NRB*ND];
__device__ float g_Wqk[ND*ND];   // Wq @ Wk^T   ([d][n])
__device__ float g_Wvo[ND*ND];   // Wv @ Wo

// dynamic smem layout for k_attn (floats)
#define OFF_WE   0
#define OFF_BE   (OFF_WE  + 1024)
#define OFF_G1   (OFF_BE  + 128)
#define OFF_B1   (OFF_G1  + 128)
#define OFF_TS   (OFF_B1  + 128)
#define OFF_LG   (OFF_TS  + 128)
#define OFF_SW   (OFF_LG  + 128)
#define OFF_RED  (OFF_SW  + 128)
#define OFF_ML   (OFF_RED + 128)
#define OFF_XS   (OFF_ML  + 4)
#define ATTN_FLOATS (OFF_XS + 128*132)
#define ATTN_SMEM   (ATTN_FLOATS*4)   // 75280 bytes

// dynamic smem layout for k_out (floats): sA[2][264], sB[2][8320]; sC reuses sB0
#define KO_SA    0
#define KO_SB    528
#define KO_SBSZ  8320
#define KO_FLOATS (KO_SB + 2*KO_SBSZ)
#define KO_SMEM   (KO_FLOATS*4)       // 68672 bytes

// mask is a bool array delivered as 32-bit elements (int32 0/1 or float32 0.0/1.0).
__device__ __forceinline__ float mask_f(const unsigned int* __restrict__ m, int idx){
    return (m[idx] != 0u) ? 1.0f : 0.0f;
}

__device__ __forceinline__ float gelu_f(float x){
    // jax gelu (tanh approx) == x * sigmoid(2*g), g = sqrt(2/pi)*(x + 0.044715 x^3)
    float x2 = x*x;
    float g  = x*(0.7978845608028654f + 0.03567740813634427f*x2);
    float e  = __expf(-2.0f*g);
    return x / (1.0f + e);
}

// ---------------------------------------------------------------------------
// k_pre: fused independent prep work, one launch, 256 threads/CTA
//   blocks [0,1024):    Xd diag rows (2 rows per CTA)
//   blocks [1024,1040): Wqk = Wq @ Wk^T  (8 out-rows per CTA, tiled)
//   blocks [1040,1056): Wvo = Wv @ Wo    (8 out-rows per CTA, tiled)
//   blocks [1056,1073): bool outputs as float
// ---------------------------------------------------------------------------
__global__ void __launch_bounds__(256) k_pre(
    const float* __restrict__ vec, const unsigned int* __restrict__ mask,
    const float* __restrict__ We,  const float* __restrict__ be,
    const float* __restrict__ g1,  const float* __restrict__ b1,
    const float* __restrict__ Wq,  const float* __restrict__ Wk,
    const float* __restrict__ Wv,  const float* __restrict__ Wo,
    float* __restrict__ out, int do_masks)
{
    __shared__ float smbuf[5248];
    int bi  = blockIdx.x;
    int tid = threadIdx.x;

    if (bi < 1024){
        // ---- diag rows: rb = bi*2 + h
        float* v8s = smbuf;        // 2*8
        float* red = smbuf + 16;   // 2*8
        int h = tid >> 7, d = tid & 127;
        int rb = bi*2 + h; int r = rb >> 4, b = rb & 15;
        const float* vp = vec + ((b*NT + r)*NT + r)*NI;
        if (d < 8) v8s[h*8 + d] = vp[d];
        float mf = mask_f(mask, (b*NT + r)*NT + r);
        __syncthreads();
        float y = be[d];
        #pragma unroll
        for (int i = 0; i < 8; i++) y += v8s[h*8 + i]*We[i*ND + d];
        y = gelu_f(y) * mf;
        float s1 = y, s2 = y*y;
        #pragma unroll
        for (int o = 16; o; o >>= 1){
            s1 += __shfl_xor_sync(0xffffffffu, s1, o);
            s2 += __shfl_xor_sync(0xffffffffu, s2, o);
        }
        int w = (tid >> 5) & 3, lane = tid & 31;
        if (lane == 0){ red[h*8 + w] = s1; red[h*8 + 4 + w] = s2; }
        __syncthreads();
        s1 = red[h*8+0]+red[h*8+1]+red[h*8+2]+red[h*8+3];
        s2 = red[h*8+4]+red[h*8+5]+red[h*8+6]+red[h*8+7];
        float mu  = s1 * (1.0f/128.0f);
        float var = s2 * (1.0f/128.0f) - mu*mu;
        g_Xd[rb*ND + d] = (y - mu)*rsqrtf(var + 1e-5f)*g1[d] + b1[d];
    } else if (bi < 1040){
        // ---- Wqk[m][n] = sum_e Wq[m][e]*Wk[n][e], rows m0..m0+7
        float* sA = smbuf;          // 8*128
        float* sB = smbuf + 1024;   // 32*129 (pitch 129, conflict-free scalar)
        int m0 = (bi - 1024)*8;
        *(float4*)&sA[tid*4] = *(const float4*)(Wq + m0*ND + tid*4);
        int m = tid >> 5, nl = tid & 31;
        for (int nt = 0; nt < 4; nt++){
            int n0 = nt*32;
            #pragma unroll
            for (int i = 0; i < 4; i++){
                int fi = tid + i*256;        // float4 index 0..1023
                int rowk = fi >> 5, col4 = fi & 31;
                float4 v = *(const float4*)(Wk + (n0+rowk)*ND + col4*4);
                float* dst = &sB[rowk*129 + col4*4];
                dst[0]=v.x; dst[1]=v.y; dst[2]=v.z; dst[3]=v.w;
            }
            __syncthreads();
            float a = 0.0f;
            #pragma unroll 8
            for (int e = 0; e < 128; e++)
                a += sA[m*128 + e] * sB[nl*129 + e];
            g_Wqk[(m0+m)*ND + n0 + nl] = a;
            __syncthreads();
        }
    } else if (bi < 1056){
        // ---- Wvo[m][n] = sum_e Wv[m][e]*Wo[e][n], rows m0..m0+7
        float* sA = smbuf;          // 8*128
        float* sB = smbuf + 1024;   // 32*132 (pitch 132)
        int m0 = (bi - 1040)*8;
        *(float4*)&sA[tid*4] = *(const float4*)(Wv + m0*ND + tid*4);
        int m = tid >> 5, tx = tid & 31;
        float4 acc = make_float4(0.f,0.f,0.f,0.f);
        for (int e0 = 0; e0 < 128; e0 += 32){
            #pragma unroll
            for (int i = 0; i < 4; i++){
                int fi = tid + i*256;
                int ee = fi >> 5, col4 = fi & 31;
                *(float4*)&sB[ee*132 + col4*4] = *(const float4*)(Wo + (e0+ee)*ND + col4*4);
            }
            __syncthreads();
            #pragma unroll 8
            for (int ee = 0; ee < 32; ee++){
                float a = sA[m*128 + e0 + ee];
                float4 b4 = *(float4*)&sB[ee*132 + tx*4];
                acc.x += a*b4.x; acc.y += a*b4.y; acc.z += a*b4.z; acc.w += a*b4.w;
            }
            __syncthreads();
        }
        *(float4*)&g_Wvo[(m0+m)*ND + tx*4] = acc;
    } else if (do_masks){
        int idx = (bi - 1056)*256 + tid;
        if (idx < 2048){
            int b = idx >> 7, t = idx & 127;
            out[262144 + idx] = (mask[(b*NT + t)*NT + t] != 0u) ? 0.0f : 1.0f;   // ~seq^T
        } else if (idx < 4096){
            int k = idx - 2048; int t = k >> 4, b = k & 15;
            out[264192 + k] = (mask[(b*NT + t)*NT + t] != 0u) ? 1.0f : 0.0f;     // seq
        } else if (idx < 4224){
            out[266240 + (idx - 4096)] = 1.0f;                                    // ones
        }
    }
}

// ---------------------------------------------------------------------------
// T = Xd @ Wqk  — tiled GEMM, 16-row CTAs (grid 128), DOUBLE-BUFFERED:
// next k-tile LDGs issue before the FMA loop, overlapping L2 latency.
// ---------------------------------------------------------------------------
__global__ void __launch_bounds__(256) k_qt()
{
    __shared__ float sA[2][16*33];
    __shared__ float sB[2][32*132];
    int tid = threadIdx.x;
    int rb0 = blockIdx.x*16;
    int tx = tid & 31, ty = tid >> 5;
    int r0 = ty*2, r1 = r0 + 1, c4 = tx*4;
    // per-thread load coordinates
    int arow0 = tid >> 5,        akk0 = tid & 31;          // i=0
    int arow1 = (tid+256) >> 5,  akk1 = (tid+256) & 31;    // i=1
    float acc[8];
    #pragma unroll
    for (int j = 0; j < 8; j++) acc[j] = 0.0f;

    // preload tile 0
    float a_pre0 = g_Xd[(rb0+arow0)*ND + akk0];
    float a_pre1 = g_Xd[(rb0+arow1)*ND + akk1];
    float4 b_pre[4];
    #pragma unroll
    for (int i = 0; i < 4; i++){
        int fi = tid + i*256; int kk = fi >> 5, cf = fi & 31;
        b_pre[i] = *(const float4*)(g_Wqk + kk*ND + cf*4);
    }
    sA[0][arow0*33 + akk0] = a_pre0;
    sA[0][arow1*33 + akk1] = a_pre1;
    #pragma unroll
    for (int i = 0; i < 4; i++){
        int fi = tid + i*256; int kk = fi >> 5, cf = fi & 31;
        *(float4*)&sB[0][kk*132 + cf*4] = b_pre[i];
    }
    __syncthreads();

    for (int kt = 0; kt < 4; kt++){
        int cur = kt & 1;
        if (kt < 3){
            int k0n = (kt+1)*32;
            a_pre0 = g_Xd[(rb0+arow0)*ND + k0n + akk0];
            a_pre1 = g_Xd[(rb0+arow1)*ND + k0n + akk1];
            #pragma unroll
            for (int i = 0; i < 4; i++){
                int fi = tid + i*256; int kk = fi >> 5, cf = fi & 31;
                b_pre[i] = *(const float4*)(g_Wqk + (k0n+kk)*ND + cf*4);
            }
        }
        #pragma unroll
        for (int kk = 0; kk < 32; kk++){
            float a0 = sA[cur][r0*33 + kk], a1 = sA[cur][r1*33 + kk];
            float4 b = *(float4*)&sB[cur][kk*132 + c4];
            acc[0] += a0*b.x; acc[1] += a0*b.y; acc[2] += a0*b.z; acc[3] += a0*b.w;
            acc[4] += a1*b.x; acc[5] += a1*b.y; acc[6] += a1*b.z; acc[7] += a1*b.w;
        }
        __syncthreads();
        if (kt < 3){
            int nb = 1 - cur;
            sA[nb][arow0*33 + akk0] = a_pre0;
            sA[nb][arow1*33 + akk1] = a_pre1;
            #pragma unroll
            for (int i = 0; i < 4; i++){
                int fi = tid + i*256; int kk = fi >> 5, cf = fi & 31;
                *(float4*)&sB[nb][kk*132 + cf*4] = b_pre[i];
            }
            __syncthreads();
        }
    }
    *(float4*)&g_T[(rb0+r0)*ND + c4] = make_float4(acc[0],acc[1],acc[2],acc[3]);
    *(float4*)&g_T[(rb0+r1)*ND + c4] = make_float4(acc[4],acc[5],acc[6],acc[7]);
}

// ---------------------------------------------------------------------------
// Fused attention. One CTA per (r,b), 256 threads, dyn smem.
// Early-exit if diagonal masked; masked c-rows skipped. (round-9 verbatim)
// ---------------------------------------------------------------------------
__global__ void __launch_bounds__(256) k_attn(
    const float* __restrict__ vec, const unsigned int* __restrict__ mask,
    const float* __restrict__ We,  const float* __restrict__ be,
    const float* __restrict__ g1,  const float* __restrict__ b1)
{
    extern __shared__ float sm[];
    float* sWe  = sm + OFF_WE;
    float* sbe  = sm + OFF_BE;
    float* sg1  = sm + OFF_G1;
    float* sb1  = sm + OFF_B1;
    float* ts   = sm + OFF_TS;
    float* slg  = sm + OFF_LG;
    float* sw   = sm + OFF_SW;
    float* sred = sm + OFF_RED;
    float* sml  = sm + OFF_ML;
    float* sxs  = sm + OFF_XS;

    int tid = threadIdx.x;
    int rb = blockIdx.x; int r = rb >> 4; int b = rb & 15;

    // early exit: masked diagonal -> output row zeroed in k_out anyway
    if (mask[(b*NT + r)*NT + r] == 0u) return;

    #pragma unroll
    for (int i = 0; i < 4; i++) sWe[tid + i*256] = We[tid + i*256];
    if (tid < 128){
        sbe[tid] = be[tid]; sg1[tid] = g1[tid]; sb1[tid] = b1[tid];
        ts[tid]  = g_T[rb*ND + tid] * 0.08838834764831845f;   // 1/sqrt(128)
    }
    __syncthreads();

    // phase 1a: embed+gelu+LN1 for c-row = tid>>1, d-half = tid&1
    int row = tid >> 1, half = tid & 1, d0 = 64*half;
    int lane = tid & 31;
    unsigned pmask = 3u << (lane & ~1);   // 2-lane pair mask (divergence-safe)
    float mf = mask_f(mask, (b*NT + r)*NT + row);
    bool active_row = (mf != 0.0f);   // row==r always active (diag unmasked)

    if (active_row){
        const float* vp = vec + (((b*NT + r)*NT) + row)*NI;
        float4 vA = *(const float4*)vp;
        float4 vB = *(const float4*)(vp + 4);
        float v8r[8] = {vA.x,vA.y,vA.z,vA.w,vB.x,vB.y,vB.z,vB.w};

        float y[64];
        float s1 = 0.0f, s2 = 0.0f;
        #pragma unroll
        for (int j = 0; j < 16; j++){
            int d = d0 + 4*j;
            float4 a4 = *(const float4*)(sbe + d);
            #pragma unroll
            for (int i = 0; i < 8; i++){
                float4 w4 = *(const float4*)(sWe + i*128 + d);
                a4.x += v8r[i]*w4.x; a4.y += v8r[i]*w4.y;
                a4.z += v8r[i]*w4.z; a4.w += v8r[i]*w4.w;
            }
            a4.x = gelu_f(a4.x); a4.y = gelu_f(a4.y);
            a4.z = gelu_f(a4.z); a4.w = gelu_f(a4.w);
            y[4*j+0]=a4.x; y[4*j+1]=a4.y; y[4*j+2]=a4.z; y[4*j+3]=a4.w;
            s1 += a4.x + a4.y + a4.z + a4.w;
            s2 += a4.x*a4.x + a4.y*a4.y + a4.z*a4.z + a4.w*a4.w;
        }
        s1 += __shfl_xor_sync(pmask, s1, 1);
        s2 += __shfl_xor_sync(pmask, s2, 1);
        float mu   = s1*(1.0f/128.0f);
        float var  = s2*(1.0f/128.0f) - mu*mu;
        float rstd = rsqrtf(var + 1e-5f);
        #pragma unroll
        for (int j = 0; j < 16; j++){
            int d = d0 + 4*j;
            float4 g4 = *(const float4*)(sg1 + d);
            float4 b4 = *(const float4*)(sb1 + d);
            float4 x4;
            x4.x = (y[4*j+0]-mu)*rstd*g4.x + b4.x;
            x4.y = (y[4*j+1]-mu)*rstd*g4.y + b4.y;
            x4.z = (y[4*j+2]-mu)*rstd*g4.z + b4.z;
            x4.w = (y[4*j+3]-mu)*rstd*g4.w + b4.w;
            *(float4*)(sxs + row*132 + d) = x4;
        }
    } else {
        // masked row: weight will be exactly 0; store zeros to keep phase 3 clean
        float4 z4 = make_float4(0.f,0.f,0.f,0.f);
        #pragma unroll
        for (int j = 0; j < 16; j++) *(float4*)(sxs + row*132 + d0 + 4*j) = z4;
        if (half == 0) slg[row] = -1e9f;
    }
    __syncthreads();

    // phase 1c: logits for active rows (pair-mask shuffle; divergent-safe)
    if (active_row){
        float dotp = 0.0f;
        #pragma unroll
        for (int j = 0; j < 16; j++){
            int d = d0 + 4*j;
            float4 x4 = *(const float4*)(sxs + row*132 + d);
            float4 t4 = *(const float4*)(ts + d);
            dotp += x4.x*t4.x + x4.y*t4.y + x4.z*t4.z + x4.w*t4.w;
        }
        dotp += __shfl_xor_sync(pmask, dotp, 1);
        if (half == 0) slg[row] = dotp;
    }
    __syncthreads();

    // phase 2: flat softmax over 128 logits (warp 0; convergent)
    if (tid < 32){
        float lgv[4];
        #pragma unroll
        for (int k = 0; k < 4; k++) lgv[k] = slg[tid + 32*k];
        float m = fmaxf(fmaxf(lgv[0],lgv[1]), fmaxf(lgv[2],lgv[3]));
        #pragma unroll
        for (int o = 16; o; o >>= 1) m = fmaxf(m, __shfl_xor_sync(0xffffffffu, m, o));
        float e[4], s = 0.0f;
        #pragma unroll
        for (int k = 0; k < 4; k++){ e[k] = __expf(lgv[k]-m); s += e[k]; }
        #pragma unroll
        for (int o = 16; o; o >>= 1) s += __shfl_xor_sync(0xffffffffu, s, o);
        #pragma unroll
        for (int k = 0; k < 4; k++) sw[tid + 32*k] = e[k];
        if (tid == 0) sml[0] = s;
    }
    __syncthreads();

    // phase 3: z[dz] = sum_c w[c] * x[c][dz]
    int dz = tid & 127, h = tid >> 7;
    float z = 0.0f;
    const float* xp = sxs + (h*64)*132 + dz;
    const float* wp = sw + h*64;
    #pragma unroll 8
    for (int c = 0; c < 64; c++) z += wp[c]*xp[c*132];
    if (h == 1) sred[dz] = z;
    __syncthreads();
    if (h == 0) g_Z[rb*ND + dz] = (z + sred[dz]) / sml[0];
}

// ---------------------------------------------------------------------------
// [E|G] = Z @ [Wv|Wvo]; t = gelu(G+bo)+E; out = LN2(t)*seq
// 8-row CTAs (grid 256), DOUBLE-BUFFERED tiled GEMM N=256 (dyn smem).
// ---------------------------------------------------------------------------
__global__ void __launch_bounds__(256) k_out(
    const float* __restrict__ Wv, const float* __restrict__ bo,
    const float* __restrict__ g2, const float* __restrict__ b2,
    const unsigned int* __restrict__ mask, float* __restrict__ out)
{
    extern __shared__ float sm[];
    // sA[buf] = sm + KO_SA + buf*264 ; sB[buf] = sm + KO_SB + buf*KO_SBSZ
    int tid = threadIdx.x;
    int rb0 = blockIdx.x*8;
    int tx = tid & 31, ty = tid >> 5;       // warp ty handles row ty
    int c8 = tx*8;
    float acc[8];
    #pragma unroll
    for (int j = 0; j < 8; j++) acc[j] = 0.0f;

    // preload tile 0
    float a_pre = g_Z[(rb0 + ty)*ND + tx];
    float4 b_pre[8];
    #pragma unroll
    for (int i = 0; i < 8; i++){
        int fi = tid + i*256; int kk = fi >> 6, cf = fi & 63;
        const float* src = (cf < 32) ? (Wv + kk*ND + cf*4)
                                     : (g_Wvo + kk*ND + (cf-32)*4);
        b_pre[i] = *(const float4*)src;
    }
    sm[KO_SA + ty*33 + tx] = a_pre;
    #pragma unroll
    for (int i = 0; i < 8; i++){
        int fi = tid + i*256; int kk = fi >> 6, cf = fi & 63;
        *(float4*)&sm[KO_SB + kk*260 + cf*4] = b_pre[i];
    }
    __syncthreads();

    for (int kt = 0; kt < 4; kt++){
        int cur = kt & 1;
        float* sAq = sm + KO_SA + cur*264;
        float* sBq = sm + KO_SB + cur*KO_SBSZ;
        if (kt < 3){
            int k0n = (kt+1)*32;
            a_pre = g_Z[(rb0 + ty)*ND + k0n + tx];
            #pragma unroll
            for (int i = 0; i < 8; i++){
                int fi = tid + i*256; int kk = fi >> 6, cf = fi & 63;
                const float* src = (cf < 32) ? (Wv + (k0n+kk)*ND + cf*4)
                                             : (g_Wvo + (k0n+kk)*ND + (cf-32)*4);
                b_pre[i] = *(const float4*)src;
            }
        }
        #pragma unroll
        for (int kk = 0; kk < 32; kk++){
            float a = sAq[ty*33 + kk];
            float4 bx = *(float4*)&sBq[kk*260 + c8];
            float4 by = *(float4*)&sBq[kk*260 + c8 + 4];
            acc[0] += a*bx.x; acc[1] += a*bx.y; acc[2] += a*bx.z; acc[3] += a*bx.w;
            acc[4] += a*by.x; acc[5] += a*by.y; acc[6] += a*by.z; acc[7] += a*by.w;
        }
        __syncthreads();
        if (kt < 3){
            int nb = 1 - cur;
            float* sAn = sm + KO_SA + nb*264;
            float* sBn = sm + KO_SB + nb*KO_SBSZ;
            sAn[ty*33 + tx] = a_pre;
            #pragma unroll
            for (int i = 0; i < 8; i++){
                int fi = tid + i*256; int kk = fi >> 6, cf = fi & 63;
                *(float4*)&sBn[kk*260 + cf*4] = b_pre[i];
            }
            __syncthreads();
        }
    }
    // stage C into sB buffer 0 (last tile read was buffer 1): row ty, cols c8..+8
    float* sC = sm + KO_SB;
    *(float4*)&sC[ty*260 + c8    ] = make_float4(acc[0],acc[1],acc[2],acc[3]);
    *(float4*)&sC[ty*260 + c8 + 4] = make_float4(acc[4],acc[5],acc[6],acc[7]);
    __syncthreads();

    // epilogue: warp ty handles row ty; lane owns d-quad tx*4
    int d4 = tx*4;
    float4 bo4 = *(const float4*)(bo + d4);
    float4 g24 = *(const float4*)(g2 + d4);
    float4 b24 = *(const float4*)(b2 + d4);
    float4 E = *(float4*)&sC[ty*260 + d4];
    float4 G = *(float4*)&sC[ty*260 + 128 + d4];
    float4 t;
    t.x = gelu_f(G.x + bo4.x) + E.x;
    t.y = gelu_f(G.y + bo4.y) + E.y;
    t.z = gelu_f(G.z + bo4.z) + E.z;
    t.w = gelu_f(G.w + bo4.w) + E.w;
    float s1 = t.x + t.y + t.z + t.w;
    float s2 = t.x*t.x + t.y*t.y + t.z*t.z + t.w*t.w;
    #pragma unroll
    for (int o = 16; o; o >>= 1){
        s1 += __shfl_xor_sync(0xffffffffu, s1, o);
        s2 += __shfl_xor_sync(0xffffffffu, s2, o);
    }
    float mu   = s1*(1.0f/128.0f);
    float var  = s2*(1.0f/128.0f) - mu*mu;
    float rstd = rsqrtf(var + 1e-5f);
    int rbg = rb0 + ty; int r = rbg >> 4, bb = rbg & 15;
    float sf = mask_f(mask, (bb*NT + r)*NT + r);
    float4 o4;
    o4.x = ((t.x - mu)*rstd*g24.x + b24.x)*sf;
    o4.y = ((t.y - mu)*rstd*g24.y + b24.y)*sf;
    o4.z = ((t.z - mu)*rstd*g24.z + b24.z)*sf;
    o4.w = ((t.w - mu)*rstd*g24.w + b24.w)*sf;
    *(float4*)(out + rbg*ND + d4) = o4;
}

extern "C" void kernel_launch(void* const* d_in, const int* in_sizes, int n_in,
                              void* d_out, int out_size)
{
    const float*        vec  = (const float*)d_in[0];
    const unsigned int* mask = (const unsigned int*)d_in[1];
    const float* We = (const float*)d_in[2];
    const float* be = (const float*)d_in[3];
    const float* g1 = (const float*)d_in[4];
    const float* b1 = (const float*)d_in[5];
    const float* Wq = (const float*)d_in[6];
    const float* Wk = (const float*)d_in[7];
    const float* Wv = (const float*)d_in[8];
    const float* Wo = (const float*)d_in[9];
    const float* bo = (const float*)d_in[10];
    const float* g2 = (const float*)d_in[11];
    const float* b2 = (const float*)d_in[12];
    float* out = (float*)d_out;

    cudaFuncSetAttribute(k_attn, cudaFuncAttributeMaxDynamicSharedMemorySize, ATTN_SMEM);
    cudaFuncSetAttribute(k_out,  cudaFuncAttributeMaxDynamicSharedMemorySize, KO_SMEM);

    int do_masks = (out_size >= 266368) ? 1 : 0;
    k_pre <<<1073, 256>>>(vec, mask, We, be, g1, b1, Wq, Wk, Wv, Wo, out, do_masks);
    k_qt  <<<NRB/16, 256>>>();
    k_attn<<<NRB, 256, ATTN_SMEM>>>(vec, mask, We, be, g1, b1);
    k_out <<<NRB/8, 256, KO_SMEM>>>(Wv, bo, g2, b2, mask, out);
    (void)in_sizes; (void)n_in;
}

// round 12
// speedup vs baseline: 1.6121x; 1.1095x over previous
#include <cuda_runtime.h>
#include <math.h>

#define NB 16
#define NT 128
#define NI 8
#define ND 128
#define NRB (NT*NB)   // 2048

// scratch (allowed: __device__ globals; zero-initialized)
__device__ float g_Xd [NRB*ND];
__device__ float g_T  [NRB*ND];
__device__ float g_Z  [NRB*ND];
__device__ float g_Wqk[ND*ND];   // Wq @ Wk^T   ([d][n])
__device__ float g_Wvo[ND*ND];   // Wv @ Wo

// dynamic smem layout for k_attn (floats)
#define OFF_WE   0
#define OFF_BE   (OFF_WE  + 1024)
#define OFF_G1   (OFF_BE  + 128)
#define OFF_B1   (OFF_G1  + 128)
#define OFF_TS   (OFF_B1  + 128)
#define OFF_LG   (OFF_TS  + 128)
#define OFF_SW   (OFF_LG  + 128)
#define OFF_RED  (OFF_SW  + 128)
#define OFF_ML   (OFF_RED + 128)
#define OFF_XS   (OFF_ML  + 4)
#define ATTN_FLOATS (OFF_XS + 128*132)
#define ATTN_SMEM   (ATTN_FLOATS*4)   // 75280 bytes

// mask is a bool array delivered as 32-bit elements (int32 0/1 or float32 0.0/1.0).
__device__ __forceinline__ float mask_f(const unsigned int* __restrict__ m, int idx){
    return (m[idx] != 0u) ? 1.0f : 0.0f;
}

__device__ __forceinline__ float gelu_f(float x){
    // jax gelu (tanh approx) == x * sigmoid(2*g), g = sqrt(2/pi)*(x + 0.044715 x^3)
    float x2 = x*x;
    float g  = x*(0.7978845608028654f + 0.03567740813634427f*x2);
    float e  = __expf(-2.0f*g);
    return x / (1.0f + e);
}

// ---------------------------------------------------------------------------
// k_pre: fused independent prep work, one launch, 256 threads/CTA
//   blocks [0,1024):    Xd diag rows (2 rows per CTA)
//   blocks [1024,1040): Wqk = Wq @ Wk^T  (8 out-rows per CTA, tiled)
//   blocks [1040,1056): Wvo = Wv @ Wo    (8 out-rows per CTA, tiled)
//   blocks [1056,1073): bool outputs as float
// ---------------------------------------------------------------------------
__global__ void __launch_bounds__(256) k_pre(
    const float* __restrict__ vec, const unsigned int* __restrict__ mask,
    const float* __restrict__ We,  const float* __restrict__ be,
    const float* __restrict__ g1,  const float* __restrict__ b1,
    const float* __restrict__ Wq,  const float* __restrict__ Wk,
    const float* __restrict__ Wv,  const float* __restrict__ Wo,
    float* __restrict__ out, int do_masks)
{
    __shared__ float smbuf[5248];
    int bi  = blockIdx.x;
    int tid = threadIdx.x;

    if (bi < 1024){
        // ---- diag rows: rb = bi*2 + h
        float* v8s = smbuf;        // 2*8
        float* red = smbuf + 16;   // 2*8
        int h = tid >> 7, d = tid & 127;
        int rb = bi*2 + h; int r = rb >> 4, b = rb & 15;
        const float* vp = vec + ((b*NT + r)*NT + r)*NI;
        if (d < 8) v8s[h*8 + d] = vp[d];
        float mf = mask_f(mask, (b*NT + r)*NT + r);
        __syncthreads();
        float y = be[d];
        #pragma unroll
        for (int i = 0; i < 8; i++) y += v8s[h*8 + i]*We[i*ND + d];
        y = gelu_f(y) * mf;
        float s1 = y, s2 = y*y;
        #pragma unroll
        for (int o = 16; o; o >>= 1){
            s1 += __shfl_xor_sync(0xffffffffu, s1, o);
            s2 += __shfl_xor_sync(0xffffffffu, s2, o);
        }
        int w = (tid >> 5) & 3, lane = tid & 31;
        if (lane == 0){ red[h*8 + w] = s1; red[h*8 + 4 + w] = s2; }
        __syncthreads();
        s1 = red[h*8+0]+red[h*8+1]+red[h*8+2]+red[h*8+3];
        s2 = red[h*8+4]+red[h*8+5]+red[h*8+6]+red[h*8+7];
        float mu  = s1 * (1.0f/128.0f);
        float var = s2 * (1.0f/128.0f) - mu*mu;
        g_Xd[rb*ND + d] = (y - mu)*rsqrtf(var + 1e-5f)*g1[d] + b1[d];
    } else if (bi < 1040){
        // ---- Wqk[m][n] = sum_e Wq[m][e]*Wk[n][e], rows m0..m0+7
        float* sA = smbuf;          // 8*128
        float* sB = smbuf + 1024;   // 32*129 (pitch 129, conflict-free scalar)
        int m0 = (bi - 1024)*8;
        *(float4*)&sA[tid*4] = *(const float4*)(Wq + m0*ND + tid*4);
        int m = tid >> 5, nl = tid & 31;
        for (int nt = 0; nt < 4; nt++){
            int n0 = nt*32;
            #pragma unroll
            for (int i = 0; i < 4; i++){
                int fi = tid + i*256;        // float4 index 0..1023
                int rowk = fi >> 5, col4 = fi & 31;
                float4 v = *(const float4*)(Wk + (n0+rowk)*ND + col4*4);
                float* dst = &sB[rowk*129 + col4*4];
                dst[0]=v.x; dst[1]=v.y; dst[2]=v.z; dst[3]=v.w;
            }
            __syncthreads();
            float a = 0.0f;
            #pragma unroll 8
            for (int e = 0; e < 128; e++)
                a += sA[m*128 + e] * sB[nl*129 + e];
            g_Wqk[(m0+m)*ND + n0 + nl] = a;
            __syncthreads();
        }
    } else if (bi < 1056){
        // ---- Wvo[m][n] = sum_e Wv[m][e]*Wo[e][n], rows m0..m0+7
        float* sA = smbuf;          // 8*128
        float* sB = smbuf + 1024;   // 32*132 (pitch 132)
        int m0 = (bi - 1040)*8;
        *(float4*)&sA[tid*4] = *(const float4*)(Wv + m0*ND + tid*4);
        int m = tid >> 5, tx = tid & 31;
        float4 acc = make_float4(0.f,0.f,0.f,0.f);
        for (int e0 = 0; e0 < 128; e0 += 32){
            #pragma unroll
            for (int i = 0; i < 4; i++){
                int fi = tid + i*256;
                int ee = fi >> 5, col4 = fi & 31;
                *(float4*)&sB[ee*132 + col4*4] = *(const float4*)(Wo + (e0+ee)*ND + col4*4);
            }
            __syncthreads();
            #pragma unroll 8
            for (int ee = 0; ee < 32; ee++){
                float a = sA[m*128 + e0 + ee];
                float4 b4 = *(float4*)&sB[ee*132 + tx*4];
                acc.x += a*b4.x; acc.y += a*b4.y; acc.z += a*b4.z; acc.w += a*b4.w;
            }
            __syncthreads();
        }
        *(float4*)&g_Wvo[(m0+m)*ND + tx*4] = acc;
    } else if (do_masks){
        int idx = (bi - 1056)*256 + tid;
        if (idx < 2048){
            int b = idx >> 7, t = idx & 127;
            out[262144 + idx] = (mask[(b*NT + t)*NT + t] != 0u) ? 0.0f : 1.0f;   // ~seq^T
        } else if (idx < 4096){
            int k = idx - 2048; int t = k >> 4, b = k & 15;
            out[264192 + k] = (mask[(b*NT + t)*NT + t] != 0u) ? 1.0f : 0.0f;     // seq
        } else if (idx < 4224){
            out[266240 + (idx - 4096)] = 1.0f;                                    // ones
        }
    }
}

// ---------------------------------------------------------------------------
// T = Xd @ Wqk  — tiled GEMM, 16-row CTAs (grid 128), double-buffered
// ---------------------------------------------------------------------------
__global__ void __launch_bounds__(256) k_qt()
{
    __shared__ float sA[2][16*33];
    __shared__ float sB[2][32*132];
    int tid = threadIdx.x;
    int rb0 = blockIdx.x*16;
    int tx = tid & 31, ty = tid >> 5;
    int r0 = ty*2, r1 = r0 + 1, c4 = tx*4;
    int arow0 = tid >> 5,        akk0 = tid & 31;
    int arow1 = (tid+256) >> 5,  akk1 = (tid+256) & 31;
    float acc[8];
    #pragma unroll
    for (int j = 0; j < 8; j++) acc[j] = 0.0f;

    float a_pre0 = g_Xd[(rb0+arow0)*ND + akk0];
    float a_pre1 = g_Xd[(rb0+arow1)*ND + akk1];
    float4 b_pre[4];
    #pragma unroll
    for (int i = 0; i < 4; i++){
        int fi = tid + i*256; int kk = fi >> 5, cf = fi & 31;
        b_pre[i] = *(const float4*)(g_Wqk + kk*ND + cf*4);
    }
    sA[0][arow0*33 + akk0] = a_pre0;
    sA[0][arow1*33 + akk1] = a_pre1;
    #pragma unroll
    for (int i = 0; i < 4; i++){
        int fi = tid + i*256; int kk = fi >> 5, cf = fi & 31;
        *(float4*)&sB[0][kk*132 + cf*4] = b_pre[i];
    }
    __syncthreads();

    for (int kt = 0; kt < 4; kt++){
        int cur = kt & 1;
        if (kt < 3){
            int k0n = (kt+1)*32;
            a_pre0 = g_Xd[(rb0+arow0)*ND + k0n + akk0];
            a_pre1 = g_Xd[(rb0+arow1)*ND + k0n + akk1];
            #pragma unroll
            for (int i = 0; i < 4; i++){
                int fi = tid + i*256; int kk = fi >> 5, cf = fi & 31;
                b_pre[i] = *(const float4*)(g_Wqk + (k0n+kk)*ND + cf*4);
            }
        }
        #pragma unroll
        for (int kk = 0; kk < 32; kk++){
            float a0 = sA[cur][r0*33 + kk], a1 = sA[cur][r1*33 + kk];
            float4 b = *(float4*)&sB[cur][kk*132 + c4];
            acc[0] += a0*b.x; acc[1] += a0*b.y; acc[2] += a0*b.z; acc[3] += a0*b.w;
            acc[4] += a1*b.x; acc[5] += a1*b.y; acc[6] += a1*b.z; acc[7] += a1*b.w;
        }
        __syncthreads();
        if (kt < 3){
            int nb = 1 - cur;
            sA[nb][arow0*33 + akk0] = a_pre0;
            sA[nb][arow1*33 + akk1] = a_pre1;
            #pragma unroll
            for (int i = 0; i < 4; i++){
                int fi = tid + i*256; int kk = fi >> 5, cf = fi & 31;
                *(float4*)&sB[nb][kk*132 + cf*4] = b_pre[i];
            }
            __syncthreads();
        }
    }
    *(float4*)&g_T[(rb0+r0)*ND + c4] = make_float4(acc[0],acc[1],acc[2],acc[3]);
    *(float4*)&g_T[(rb0+r1)*ND + c4] = make_float4(acc[4],acc[5],acc[6],acc[7]);
}

// ---------------------------------------------------------------------------
// Fused attention. One CTA per (r,b), 256 threads, dyn smem.
// Early-exit if diagonal masked; masked c-rows skipped.
// ---------------------------------------------------------------------------
__global__ void __launch_bounds__(256) k_attn(
    const float* __restrict__ vec, const unsigned int* __restrict__ mask,
    const float* __restrict__ We,  const float* __restrict__ be,
    const float* __restrict__ g1,  const float* __restrict__ b1)
{
    extern __shared__ float sm[];
    float* sWe  = sm + OFF_WE;
    float* sbe  = sm + OFF_BE;
    float* sg1  = sm + OFF_G1;
    float* sb1  = sm + OFF_B1;
    float* ts   = sm + OFF_TS;
    float* slg  = sm + OFF_LG;
    float* sw   = sm + OFF_SW;
    float* sred = sm + OFF_RED;
    float* sml  = sm + OFF_ML;
    float* sxs  = sm + OFF_XS;

    int tid = threadIdx.x;
    int rb = blockIdx.x; int r = rb >> 4; int b = rb & 15;

    // early exit: masked diagonal -> output row zeroed in k_out anyway
    if (mask[(b*NT + r)*NT + r] == 0u) return;

    #pragma unroll
    for (int i = 0; i < 4; i++) sWe[tid + i*256] = We[tid + i*256];
    if (tid < 128){
        sbe[tid] = be[tid]; sg1[tid] = g1[tid]; sb1[tid] = b1[tid];
        ts[tid]  = g_T[rb*ND + tid] * 0.08838834764831845f;   // 1/sqrt(128)
    }
    __syncthreads();

    // phase 1a: embed+gelu+LN1 for c-row = tid>>1, d-half = tid&1
    int row = tid >> 1, half = tid & 1, d0 = 64*half;
    int lane = tid & 31;
    unsigned pmask = 3u << (lane & ~1);   // 2-lane pair mask (divergence-safe)
    float mf = mask_f(mask, (b*NT + r)*NT + row);
    bool active_row = (mf != 0.0f);   // row==r always active (diag unmasked)

    if (active_row){
        const float* vp = vec + (((b*NT + r)*NT) + row)*NI;
        float4 vA = *(const float4*)vp;
        float4 vB = *(const float4*)(vp + 4);
        float v8r[8] = {vA.x,vA.y,vA.z,vA.w,vB.x,vB.y,vB.z,vB.w};

        float y[64];
        float s1 = 0.0f, s2 = 0.0f;
        #pragma unroll
        for (int j = 0; j < 16; j++){
            int d = d0 + 4*j;
            float4 a4 = *(const float4*)(sbe + d);
            #pragma unroll
            for (int i = 0; i < 8; i++){
                float4 w4 = *(const float4*)(sWe + i*128 + d);
                a4.x += v8r[i]*w4.x; a4.y += v8r[i]*w4.y;
                a4.z += v8r[i]*w4.z; a4.w += v8r[i]*w4.w;
            }
            a4.x = gelu_f(a4.x); a4.y = gelu_f(a4.y);
            a4.z = gelu_f(a4.z); a4.w = gelu_f(a4.w);
            y[4*j+0]=a4.x; y[4*j+1]=a4.y; y[4*j+2]=a4.z; y[4*j+3]=a4.w;
            s1 += a4.x + a4.y + a4.z + a4.w;
            s2 += a4.x*a4.x + a4.y*a4.y + a4.z*a4.z + a4.w*a4.w;
        }
        s1 += __shfl_xor_sync(pmask, s1, 1);
        s2 += __shfl_xor_sync(pmask, s2, 1);
        float mu   = s1*(1.0f/128.0f);
        float var  = s2*(1.0f/128.0f) - mu*mu;
        float rstd = rsqrtf(var + 1e-5f);
        #pragma unroll
        for (int j = 0; j < 16; j++){
            int d = d0 + 4*j;
            float4 g4 = *(const float4*)(sg1 + d);
            float4 b4 = *(const float4*)(sb1 + d);
            float4 x4;
            x4.x = (y[4*j+0]-mu)*rstd*g4.x + b4.x;
            x4.y = (y[4*j+1]-mu)*rstd*g4.y + b4.y;
            x4.z = (y[4*j+2]-mu)*rstd*g4.z + b4.z;
            x4.w = (y[4*j+3]-mu)*rstd*g4.w + b4.w;
            *(float4*)(sxs + row*132 + d) = x4;
        }
    } else {
        // masked row: weight will be exactly 0; store zeros to keep phase 3 clean
        float4 z4 = make_float4(0.f,0.f,0.f,0.f);
        #pragma unroll
        for (int j = 0; j < 16; j++) *(float4*)(sxs + row*132 + d0 + 4*j) = z4;
        if (half == 0) slg[row] = -1e9f;
    }
    __syncthreads();

    // phase 1c: logits for active rows (pair-mask shuffle; divergent-safe)
    if (active_row){
        float dotp = 0.0f;
        #pragma unroll
        for (int j = 0; j < 16; j++){
            int d = d0 + 4*j;
            float4 x4 = *(const float4*)(sxs + row*132 + d);
            float4 t4 = *(const float4*)(ts + d);
            dotp += x4.x*t4.x + x4.y*t4.y + x4.z*t4.z + x4.w*t4.w;
        }
        dotp += __shfl_xor_sync(pmask, dotp, 1);
        if (half == 0) slg[row] = dotp;
    }
    __syncthreads();

    // phase 2: flat softmax over 128 logits (warp 0; convergent)
    if (tid < 32){
        float lgv[4];
        #pragma unroll
        for (int k = 0; k < 4; k++) lgv[k] = slg[tid + 32*k];
        float m = fmaxf(fmaxf(lgv[0],lgv[1]), fmaxf(lgv[2],lgv[3]));
        #pragma unroll
        for (int o = 16; o; o >>= 1) m = fmaxf(m, __shfl_xor_sync(0xffffffffu, m, o));
        float e[4], s = 0.0f;
        #pragma unroll
        for (int k = 0; k < 4; k++){ e[k] = __expf(lgv[k]-m); s += e[k]; }
        #pragma unroll
        for (int o = 16; o; o >>= 1) s += __shfl_xor_sync(0xffffffffu, s, o);
        #pragma unroll
        for (int k = 0; k < 4; k++) sw[tid + 32*k] = e[k];
        if (tid == 0) sml[0] = s;
    }
    __syncthreads();

    // phase 3: z[d] = sum_c w[c]*x[c][d]  — 4 c-groups x float2 per thread
    int d2 = (tid & 63)*2, q = tid >> 6;   // q in 0..3, 32 c-rows each
    float2 z2 = make_float2(0.f, 0.f);
    const float* wp = sw + q*32;
    const float* xp = sxs + (q*32)*132 + d2;
    #pragma unroll 8
    for (int c = 0; c < 32; c++){
        float w = wp[c];
        float2 x2 = *(const float2*)(xp + c*132);
        z2.x += w*x2.x; z2.y += w*x2.y;
    }
    // partials for q=1,2,3 via reusable smem (slg/ts/sred all dead now)
    if (q == 1){ *(float2*)(slg  + d2) = z2; }
    else if (q == 2){ *(float2*)(ts   + d2) = z2; }
    else if (q == 3){ *(float2*)(sred + d2) = z2; }
    __syncthreads();
    if (q == 0){
        float2 p1 = *(float2*)(slg  + d2);
        float2 p2 = *(float2*)(ts   + d2);
        float2 p3 = *(float2*)(sred + d2);
        float inv = 1.0f / sml[0];
        float2 o2;
        o2.x = (z2.x + p1.x + p2.x + p3.x)*inv;
        o2.y = (z2.y + p1.y + p2.y + p3.y)*inv;
        *(float2*)(g_Z + rb*ND + d2) = o2;
    }
}

// ---------------------------------------------------------------------------
// [E|G] = Z @ [Wv|Wvo]; t = gelu(G+bo)+E; out = LN2(t)*seq
// 8-row CTAs (grid 256). Conflict-free B reads (16B lane stride); E/G stay
// in registers through the epilogue (no C staging).
// ---------------------------------------------------------------------------
__global__ void __launch_bounds__(256) k_out(
    const float* __restrict__ Wv, const float* __restrict__ bo,
    const float* __restrict__ g2, const float* __restrict__ b2,
    const unsigned int* __restrict__ mask, float* __restrict__ out)
{
    __shared__ float sA[8*33];
    __shared__ float sB[32*260];   // row kk: [E cols 0..127][G cols 0..127][pad]
    int tid = threadIdx.x;
    int rb0 = blockIdx.x*8;
    int tx = tid & 31, ty = tid >> 5;     // warp ty owns row ty; lane tx owns d-quad tx*4
    float4 accE = make_float4(0.f,0.f,0.f,0.f);
    float4 accG = make_float4(0.f,0.f,0.f,0.f);

    for (int k0 = 0; k0 < 128; k0 += 32){
        sA[ty*33 + tx] = g_Z[(rb0 + ty)*ND + k0 + tx];
        #pragma unroll
        for (int i = 0; i < 8; i++){
            int fi = tid + i*256; int kk = fi >> 6, cf = fi & 63;
            const float* src = (cf < 32) ? (Wv + (k0+kk)*ND + cf*4)
                                         : (g_Wvo + (k0+kk)*ND + (cf-32)*4);
            *(float4*)&sB[kk*260 + cf*4] = *(const float4*)src;
        }
        __syncthreads();
        #pragma unroll
        for (int kk = 0; kk < 32; kk++){
            float a = sA[ty*33 + kk];                      // broadcast
            float4 bE = *(float4*)&sB[kk*260 + tx*4];      // 16B stride: conflict-free
            float4 bG = *(float4*)&sB[kk*260 + 128 + tx*4];
            accE.x += a*bE.x; accE.y += a*bE.y; accE.z += a*bE.z; accE.w += a*bE.w;
            accG.x += a*bG.x; accG.y += a*bG.y; accG.z += a*bG.z; accG.w += a*bG.w;
        }
        __syncthreads();
    }

    // epilogue entirely in registers (E/G already owned by the right lanes)
    int d4 = tx*4;
    float4 bo4 = *(const float4*)(bo + d4);
    float4 g24 = *(const float4*)(g2 + d4);
    float4 b24 = *(const float4*)(b2 + d4);
    float4 t;
    t.x = gelu_f(accG.x + bo4.x) + accE.x;
    t.y = gelu_f(accG.y + bo4.y) + accE.y;
    t.z = gelu_f(accG.z + bo4.z) + accE.z;
    t.w = gelu_f(accG.w + bo4.w) + accE.w;
    float s1 = t.x + t.y + t.z + t.w;
    float s2 = t.x*t.x + t.y*t.y + t.z*t.z + t.w*t.w;
    #pragma unroll
    for (int o = 16; o; o >>= 1){
        s1 += __shfl_xor_sync(0xffffffffu, s1, o);
        s2 += __shfl_xor_sync(0xffffffffu, s2, o);
    }
    float mu   = s1*(1.0f/128.0f);
    float var  = s2*(1.0f/128.0f) - mu*mu;
    float rstd = rsqrtf(var + 1e-5f);
    int rbg = rb0 + ty; int r = rbg >> 4, bb = rbg & 15;
    float sf = mask_f(mask, (bb*NT + r)*NT + r);
    float4 o4;
    o4.x = ((t.x - mu)*rstd*g24.x + b24.x)*sf;
    o4.y = ((t.y - mu)*rstd*g24.y + b24.y)*sf;
    o4.z = ((t.z - mu)*rstd*g24.z + b24.z)*sf;
    o4.w = ((t.w - mu)*rstd*g24.w + b24.w)*sf;
    *(float4*)(out + rbg*ND + d4) = o4;
}

extern "C" void kernel_launch(void* const* d_in, const int* in_sizes, int n_in,
                              void* d_out, int out_size)
{
    const float*        vec  = (const float*)d_in[0];
    const unsigned int* mask = (const unsigned int*)d_in[1];
    const float* We = (const float*)d_in[2];
    const float* be = (const float*)d_in[3];
    const float* g1 = (const float*)d_in[4];
    const float* b1 = (const float*)d_in[5];
    const float* Wq = (const float*)d_in[6];
    const float* Wk = (const float*)d_in[7];
    const float* Wv = (const float*)d_in[8];
    const float* Wo = (const float*)d_in[9];
    const float* bo = (const float*)d_in[10];
    const float* g2 = (const float*)d_in[11];
    const float* b2 = (const float*)d_in[12];
    float* out = (float*)d_out;

    cudaFuncSetAttribute(k_attn, cudaFuncAttributeMaxDynamicSharedMemorySize, ATTN_SMEM);

    int do_masks = (out_size >= 266368) ? 1 : 0;
    k_pre <<<1073, 256>>>(vec, mask, We, be, g1, b1, Wq, Wk, Wv, Wo, out, do_masks);
    k_qt  <<<NRB/16, 256>>>();
    k_attn<<<NRB, 256, ATTN_SMEM>>>(vec, mask, We, be, g1, b1);
    k_out <<<NRB/8, 256>>>(Wv, bo, g2, b2, mask, out);
    (void)in_sizes; (void)n_in;
}